// round 11
// baseline (speedup 1.0000x reference)
#include <cuda_runtime.h>
#include <cuda_fp16.h>
#include <cstdint>

// Problem constants
#define SEQ     4096
#define BATCH   8
#define CH      256
#define M_TOT   (SEQ*BATCH)      // 32768 rows (t-major, b inner: m = t*8 + b)
#define KDIM    512              // virtual K = 2 taps x 256 channels
#define NDIM    512              // interleaved: even n = Z col n/2, odd n = F col n/2
#define NCHUNK  512              // 8-timestep chunks
#define NGROUP  128              // groups of 4 chunks (32 timesteps)
#define GSTEP   32
#define BHTOT   2048             // BATCH*CH

// Scratch (static device globals; runtime allocation forbidden)
__device__ __half2 g_G[M_TOT*CH];           // per (t,b,h): (a=1-f, g=f*z) fp16
__device__ __half g_Xh[M_TOT*CH];
__device__ __half g_Wp[NDIM*KDIM];          // [n][k] K-major fp16, Z/F interleaved
__device__ float g_biasf[NDIM];             // interleaved bias
__device__ float2 g_cAB[NCHUNK*BHTOT];      // 8-step chunk affine (A,B), [c][bh]
__device__ float g_gH[NGROUP*BHTOT];        // group starting hidden state, [g][bh]

__device__ __forceinline__ float sigf(float x) {
    return __fdividef(1.0f, 1.0f + __expf(-x));
}

__device__ __forceinline__ uint32_t smem_u32(const void* p) {
    return (uint32_t)__cvta_generic_to_shared(p);
}

// ---------------------------------------------------------------------------
// Portable primitives: cp.async, ldmatrix, mma.sync fp16
// ---------------------------------------------------------------------------
__device__ __forceinline__ void cp_async16(uint32_t dst, const void* src, uint32_t sz) {
    asm volatile("cp.async.cg.shared.global [%0], [%1], 16, %2;"
                 :: "r"(dst), "l"(src), "r"(sz) : "memory");
}
#define CP_COMMIT() asm volatile("cp.async.commit_group;" ::: "memory")
#define CP_WAIT(n)  asm volatile("cp.async.wait_group %0;" :: "n"(n) : "memory")

__device__ __forceinline__ void ldsm_x4(uint32_t* r, uint32_t addr) {
    asm volatile("ldmatrix.sync.aligned.m8n8.x4.shared.b16 {%0,%1,%2,%3}, [%4];"
                 : "=r"(r[0]), "=r"(r[1]), "=r"(r[2]), "=r"(r[3]) : "r"(addr));
}
__device__ __forceinline__ void ldsm_x2(uint32_t* r, uint32_t addr) {
    asm volatile("ldmatrix.sync.aligned.m8n8.x2.shared.b16 {%0,%1}, [%2];"
                 : "=r"(r[0]), "=r"(r[1]) : "r"(addr));
}
__device__ __forceinline__ void mma_f16(float* d, const uint32_t* a, const uint32_t* b) {
    asm volatile(
        "mma.sync.aligned.m16n8k16.row.col.f32.f16.f16.f32 "
        "{%0,%1,%2,%3}, {%4,%5,%6,%7}, {%8,%9}, {%0,%1,%2,%3};"
        : "+f"(d[0]), "+f"(d[1]), "+f"(d[2]), "+f"(d[3])
        : "r"(a[0]), "r"(a[1]), "r"(a[2]), "r"(a[3]), "r"(b[0]), "r"(b[1]));
}

// ---------------------------------------------------------------------------
// prep: convert X -> fp16 AND pack interleaved fp16 weights + bias
// ---------------------------------------------------------------------------
__global__ void prep(const float* __restrict__ X,
                     const float* __restrict__ Wz, const float* __restrict__ bz,
                     const float* __restrict__ Wf, const float* __restrict__ bf) {
    int i = blockIdx.x * 256 + threadIdx.x;
    float4 v = reinterpret_cast<const float4*>(X)[i];
    __half2* ph = reinterpret_cast<__half2*>(g_Xh);
    ph[i * 2 + 0] = __half2(__float2half_rn(v.x), __float2half_rn(v.y));
    ph[i * 2 + 1] = __half2(__float2half_rn(v.z), __float2half_rn(v.w));
    if (i < NDIM * KDIM) {
        int n = i >> 9, k = i & 511;
        int h = n >> 1;
        int c   = (k < 256) ? k : (k - 256);
        int tap = (k < 256) ? 0 : 1;
        float w = ((n & 1) == 0) ? Wz[h * 512 + c * 2 + tap]
                                 : Wf[h * 512 + c * 2 + tap];
        g_Wp[i] = __float2half_rn(w);
    }
    if (i < NDIM) g_biasf[i] = ((i & 1) == 0) ? bz[i >> 1] : bf[i >> 1];
}

// ---------------------------------------------------------------------------
// HMMA GEMM + fused gate epilogue + 8-step chunk composition.
// CTA tile 128(M) x 128(N); grid = (4 n-tiles, 256 m-tiles); 2 CTAs/SM.
// 8 warps = 2M x 4N; warp tile 64x32.
// m = t*8 + b: lane owns batch b=lane>>2, timesteps t = by*16+mwarp*8+mf*2+half.
// Epilogue: activations -> (a,g) fp16 gates staged via smem (coalesced out)
// + per-8-step-chunk affine (A,B) as float2.
// ---------------------------------------------------------------------------
#define LDS_ROW  80
#define A_TILE   (128*LDS_ROW)         // 10240 B
#define B_TILE   (128*LDS_ROW)         // 10240 B
#define STAGE_B  (A_TILE + B_TILE)     // 20480 B
#define NSTAGE   4
#define SMEM_GEMM (NSTAGE*STAGE_B)     // 81920 B

__global__ void __launch_bounds__(256, 2)
gemm_mma() {
    extern __shared__ char smem[];
    const uint32_t sb = smem_u32(smem);
    const int tid  = threadIdx.x;
    const int lane = tid & 31;
    const int wid  = tid >> 5;
    const int mwarp = wid & 1;          // 2 warps along M (64 rows each)
    const int nwarp = wid >> 1;         // 4 warps along N (32 cols each)
    const int m0 = blockIdx.y * 128;
    const int n0 = blockIdx.x * 128;

    auto load_stage = [&](int s) {
        const int kb = s * 32;
        const int tap = (kb < 256) ? 0 : 1;
        const int xcol = kb - tap * 256;
        const int rowoff = tap ? 0 : -8;
        const uint32_t base = sb + (s & (NSTAGE - 1)) * STAGE_B;
#pragma unroll
        for (int q = 0; q < 4; q++) {
            const int idx = q * 256 + tid;
            if (q < 2) {                 // A : ids 0..511 (128 rows x 4 chunks)
                int row = idx >> 2, c = idx & 3;
                int gm = m0 + row + rowoff;
                int gmc = (gm >= 0) ? gm : 0;
                cp_async16(base + row * LDS_ROW + c * 16,
                           g_Xh + gmc * CH + xcol + c * 8, (gm >= 0) ? 16u : 0u);
            } else {                     // B : ids 0..511 (128 rows x 4 chunks)
                int i2 = idx - 512;
                int row = i2 >> 2, c = i2 & 3;
                cp_async16(base + A_TILE + row * LDS_ROW + c * 16,
                           g_Wp + (n0 + row) * KDIM + kb + c * 8, 16u);
            }
        }
    };

    float acc[4][4][4];
#pragma unroll
    for (int i = 0; i < 4; i++)
#pragma unroll
        for (int j = 0; j < 4; j++)
#pragma unroll
            for (int q = 0; q < 4; q++) acc[i][j][q] = 0.0f;

    const uint32_t a_off = (mwarp * 64 + (lane & 15)) * LDS_ROW + (lane >> 4) * 16;
    const uint32_t b_off = (nwarp * 32 + (lane & 7)) * LDS_ROW + ((lane >> 3) & 1) * 16;

    load_stage(0); CP_COMMIT();
    load_stage(1); CP_COMMIT();
    load_stage(2); CP_COMMIT();

    for (int s = 0; s < 16; s++) {
        CP_WAIT(2);                 // stage s resident (3 groups in flight)
        __syncthreads();            // all warps done reading buffer (s-1)&3
        if (s + 3 < 16) load_stage(s + 3);
        CP_COMMIT();                // empty group keeps WAIT(2) exact

        const uint32_t base = sb + (s & (NSTAGE - 1)) * STAGE_B;
#pragma unroll
        for (int kk = 0; kk < 2; kk++) {
            uint32_t aH[4][4];
#pragma unroll
            for (int mf = 0; mf < 4; mf++)
                ldsm_x4(aH[mf], base + a_off + mf * 16 * LDS_ROW + kk * 32);
#pragma unroll
            for (int nf = 0; nf < 4; nf++) {
                uint32_t b[2];
                ldsm_x2(b, base + A_TILE + b_off + nf * 8 * LDS_ROW + kk * 32);
#pragma unroll
                for (int mf = 0; mf < 4; mf++)
                    mma_f16(acc[mf][nf], aH[mf], b);
            }
        }
    }

    // ---- fused epilogue ----
    // b = lane>>2; t = by*16 + mwarp*8 + mf*2 + half.
    // h = (n0 + nwarp*32 + nf*8 + t4*2)>>1 = h0 + nwarp*16 + nf*4 + t4.
    __syncthreads();   // done with smem stage buffers; reuse for gate staging
    __half2* gtile = reinterpret_cast<__half2*>(smem);   // [16 t][8 b][68 pad]
    const int g4 = lane >> 2;             // batch b
    const int t4 = lane & 3;
    const int c_id = blockIdx.y * 2 + mwarp;   // 8-step chunk id
    const int h0 = n0 >> 1;
    const int bh_b = g4 * CH;

#pragma unroll
    for (int nf = 0; nf < 4; nf++) {
        const int n = n0 + nwarp * 32 + nf * 8 + t4 * 2;
        const int hl = nwarp * 16 + nf * 4 + t4;         // local h (0..63)
        const float bZ = g_biasf[n];
        const float bF = g_biasf[n + 1];
        float A = 1.0f, B = 0.0f;
#pragma unroll
        for (int mf = 0; mf < 4; mf++) {
#pragma unroll
            for (int half = 0; half < 2; half++) {
                float vz = acc[mf][nf][half * 2 + 0] + bZ;
                float vf = acc[mf][nf][half * 2 + 1] + bF;
                float z = vz * sigf(1.702f * vz);
                float f = sigf(vf);
                __half ah = __float2half_rn(1.0f - f);
                __half gh = __float2half_rn(f * z);
                const int tl = mwarp * 8 + mf * 2 + half;   // local t (0..15)
                gtile[tl * 544 + g4 * 68 + hl] = __halves2half2(ah, gh);
                float af = __half2float(ah);
                float gf = __half2float(gh);
                A *= af;
                B = fmaf(af, B, gf);
            }
        }
        g_cAB[c_id * BHTOT + bh_b + h0 + hl] = make_float2(A, B);
    }
    __syncthreads();

    // coalesced copy-out: 16 t x 8 b x 64 h = 8192 half2
    const int tg0 = blockIdx.y * 16;
#pragma unroll
    for (int it = 0; it < 32; it++) {
        int i = it * 256 + tid;
        int t = i >> 9, r = i & 511;
        int b = r >> 6, hh = r & 63;
        g_G[(tg0 + t) * BHTOT + b * CH + h0 + hh] = gtile[t * 544 + b * 68 + hh];
    }
}

// ---------------------------------------------------------------------------
// scan2w: one warp per (b,h) lane. Lane L composes chunks [16L, 16L+16)
// into 4 sub-affines of 4 chunks (= groups 4L..4L+3, GSTEP=32);
// warp-scan (Hillis-Steele, affine compose) produces all 128 group starting
// states; writes g_gH + h_last.
// grid = 256 blocks x 256 threads (2048 warps).
// Affine compose (x then y): (Ax*Ay, Ay*Bx + By).
// ---------------------------------------------------------------------------
__global__ void __launch_bounds__(256)
scan2w(const float* __restrict__ hidden, float* __restrict__ out) {
    const int lane = threadIdx.x & 31;
    const int bh = (blockIdx.x * 256 + threadIdx.x) >> 5;   // warp id = bh

    // load 16 chunk affines (independent 8B loads, high MLP)
    float2 v[16];
#pragma unroll
    for (int i = 0; i < 16; i++)
        v[i] = g_cAB[(lane * 16 + i) * BHTOT + bh];

    // compose 4 groups of 4 chunks each
    float gA[4], gB[4];
#pragma unroll
    for (int g = 0; g < 4; g++) {
        float A = v[g * 4].x, B = v[g * 4].y;
#pragma unroll
        for (int i = 1; i < 4; i++) {
            B = fmaf(v[g * 4 + i].x, B, v[g * 4 + i].y);
            A *= v[g * 4 + i].x;
        }
        gA[g] = A; gB[g] = B;
    }
    // lane affine = g0 then g1 then g2 then g3
    float LA = gA[0], LB = gB[0];
#pragma unroll
    for (int g = 1; g < 4; g++) {
        LB = fmaf(gA[g], LB, gB[g]);
        LA *= gA[g];
    }

    // inclusive warp scan (non-commutative compose, lane order)
    float sA = LA, sB = LB;
#pragma unroll
    for (int off = 1; off < 32; off <<= 1) {
        float pA = __shfl_up_sync(0xFFFFFFFFu, sA, off);
        float pB = __shfl_up_sync(0xFFFFFFFFu, sB, off);
        if (lane >= off) {
            sB = fmaf(sA, pB, sB);      // (p then s): A = pA*sA, B = sA*pB + sB
            sA = pA * sA;
        }
    }
    // exclusive prefix
    float eA = __shfl_up_sync(0xFFFFFFFFu, sA, 1);
    float eB = __shfl_up_sync(0xFFFFFFFFu, sB, 1);
    if (lane == 0) { eA = 1.0f; eB = 0.0f; }

    const float h0 = hidden[bh];
    float h = fmaf(eA, h0, eB);                      // start of group 4*lane
#pragma unroll
    for (int g = 0; g < 4; g++) {
        g_gH[(4 * lane + g) * BHTOT + bh] = h;
        h = fmaf(gA[g], h, gB[g]);
    }

    if (lane == 31)
        out[SEQ * BHTOT + bh] = fmaf(sA, h0, sB);    // h_last
}

// ---------------------------------------------------------------------------
// scan3: replay 32-step groups from fp16 gates, 4 bh-lanes per thread
// (16B vector loads/stores, 4 independent h-chains).
// grid (2, 128) x 256 threads.
// ---------------------------------------------------------------------------
__global__ void __launch_bounds__(256)
scan3(float* __restrict__ out) {
    const int q  = blockIdx.x * 256 + threadIdx.x;   // 0..511
    const int bh = q * 4;
    const int g  = blockIdx.y;

    float4 h = *reinterpret_cast<const float4*>(g_gH + g * BHTOT + bh);
    const int tbase = g * GSTEP;
#pragma unroll 8
    for (int t = 0; t < GSTEP; t++) {
        const int idx = (tbase + t) * BHTOT + bh;
        uint4 raw = *reinterpret_cast<const uint4*>(g_G + idx);
        float2 a0 = __half22float2(*reinterpret_cast<__half2*>(&raw.x));
        float2 a1 = __half22float2(*reinterpret_cast<__half2*>(&raw.y));
        float2 a2 = __half22float2(*reinterpret_cast<__half2*>(&raw.z));
        float2 a3 = __half22float2(*reinterpret_cast<__half2*>(&raw.w));
        h.x = fmaf(a0.x, h.x, a0.y);
        h.y = fmaf(a1.x, h.y, a1.y);
        h.z = fmaf(a2.x, h.z, a2.y);
        h.w = fmaf(a3.x, h.w, a3.y);
        *reinterpret_cast<float4*>(out + idx) = h;
    }
}

// ---------------------------------------------------------------------------
extern "C" void kernel_launch(void* const* d_in, const int* in_sizes, int n_in,
                              void* d_out, int out_size) {
    const float* X      = (const float*)d_in[0];
    const float* hidden = (const float*)d_in[1];
    const float* Wz     = (const float*)d_in[2];
    const float* bz     = (const float*)d_in[3];
    const float* Wf     = (const float*)d_in[4];
    const float* bf     = (const float*)d_in[5];
    float* out = (float*)d_out;

    prep<<<M_TOT * CH / 4 / 256, 256>>>(X, Wz, bz, Wf, bf);

    cudaFuncSetAttribute(gemm_mma, cudaFuncAttributeMaxDynamicSharedMemorySize, SMEM_GEMM);
    gemm_mma<<<dim3(4, 256), 256, SMEM_GEMM>>>();

    scan2w<<<BHTOT / 8, 256>>>(hidden, out);
    scan3<<<dim3(2, NGROUP), 256>>>(out);
}

// round 12
// speedup vs baseline: 1.0165x; 1.0165x over previous
#include <cuda_runtime.h>
#include <cuda_fp16.h>
#include <cstdint>

// Problem constants
#define SEQ     4096
#define BATCH   8
#define CH      256
#define M_TOT   (SEQ*BATCH)      // 32768 rows (t-major, b inner: m = t*8 + b)
#define KDIM    512              // virtual K = 2 taps x 256 channels
#define NDIM    512              // interleaved: even n = Z col n/2, odd n = F col n/2
#define NCHUNK  512              // 8-timestep chunks
#define NGROUP  256              // groups of 2 chunks (16 timesteps)
#define GSTEP   16
#define BHTOT   2048             // BATCH*CH

// Scratch (static device globals; runtime allocation forbidden)
__device__ __half2 g_G[M_TOT*CH];           // per (t,b,h): (a=1-f, g=f*z) fp16
__device__ __half g_Xh[M_TOT*CH];
__device__ __half g_Wp[NDIM*KDIM];          // [n][k] K-major fp16, Z/F interleaved
__device__ float g_biasf[NDIM];             // interleaved bias
__device__ float2 g_cAB[NCHUNK*BHTOT];      // 8-step chunk affine (A,B), [c][bh]
__device__ float g_gH[NGROUP*BHTOT];        // group starting hidden state, [g][bh]

__device__ __forceinline__ float sigf(float x) {
    return __fdividef(1.0f, 1.0f + __expf(-x));
}

__device__ __forceinline__ uint32_t smem_u32(const void* p) {
    return (uint32_t)__cvta_generic_to_shared(p);
}

// ---------------------------------------------------------------------------
// Portable primitives: cp.async, ldmatrix, mma.sync fp16
// ---------------------------------------------------------------------------
__device__ __forceinline__ void cp_async16(uint32_t dst, const void* src, uint32_t sz) {
    asm volatile("cp.async.cg.shared.global [%0], [%1], 16, %2;"
                 :: "r"(dst), "l"(src), "r"(sz) : "memory");
}
#define CP_COMMIT() asm volatile("cp.async.commit_group;" ::: "memory")
#define CP_WAIT(n)  asm volatile("cp.async.wait_group %0;" :: "n"(n) : "memory")

__device__ __forceinline__ void ldsm_x4(uint32_t* r, uint32_t addr) {
    asm volatile("ldmatrix.sync.aligned.m8n8.x4.shared.b16 {%0,%1,%2,%3}, [%4];"
                 : "=r"(r[0]), "=r"(r[1]), "=r"(r[2]), "=r"(r[3]) : "r"(addr));
}
__device__ __forceinline__ void ldsm_x2(uint32_t* r, uint32_t addr) {
    asm volatile("ldmatrix.sync.aligned.m8n8.x2.shared.b16 {%0,%1}, [%2];"
                 : "=r"(r[0]), "=r"(r[1]) : "r"(addr));
}
__device__ __forceinline__ void mma_f16(float* d, const uint32_t* a, const uint32_t* b) {
    asm volatile(
        "mma.sync.aligned.m16n8k16.row.col.f32.f16.f16.f32 "
        "{%0,%1,%2,%3}, {%4,%5,%6,%7}, {%8,%9}, {%0,%1,%2,%3};"
        : "+f"(d[0]), "+f"(d[1]), "+f"(d[2]), "+f"(d[3])
        : "r"(a[0]), "r"(a[1]), "r"(a[2]), "r"(a[3]), "r"(b[0]), "r"(b[1]));
}

// ---------------------------------------------------------------------------
// prep: convert X -> fp16 AND pack interleaved fp16 weights + bias
// ---------------------------------------------------------------------------
__global__ void prep(const float* __restrict__ X,
                     const float* __restrict__ Wz, const float* __restrict__ bz,
                     const float* __restrict__ Wf, const float* __restrict__ bf) {
    int i = blockIdx.x * 256 + threadIdx.x;
    float4 v = reinterpret_cast<const float4*>(X)[i];
    __half2* ph = reinterpret_cast<__half2*>(g_Xh);
    ph[i * 2 + 0] = __half2(__float2half_rn(v.x), __float2half_rn(v.y));
    ph[i * 2 + 1] = __half2(__float2half_rn(v.z), __float2half_rn(v.w));
    if (i < NDIM * KDIM) {
        int n = i >> 9, k = i & 511;
        int h = n >> 1;
        int c   = (k < 256) ? k : (k - 256);
        int tap = (k < 256) ? 0 : 1;
        float w = ((n & 1) == 0) ? Wz[h * 512 + c * 2 + tap]
                                 : Wf[h * 512 + c * 2 + tap];
        g_Wp[i] = __float2half_rn(w);
    }
    if (i < NDIM) g_biasf[i] = ((i & 1) == 0) ? bz[i >> 1] : bf[i >> 1];
}

// ---------------------------------------------------------------------------
// HMMA GEMM + fused gate epilogue + 8-step chunk composition.
// CTA tile 128(M) x 128(N); grid = (4 n-tiles, 256 m-tiles); 2 CTAs/SM.
// 8 warps = 2M x 4N; warp tile 64x32.
// m = t*8 + b: lane owns batch b=lane>>2, timesteps t = by*16+mwarp*8+mf*2+half.
// Epilogue: activations -> (a,g) fp16 gates staged via smem (coalesced out)
// + per-8-step-chunk affine (A,B) as float2.
// ---------------------------------------------------------------------------
#define LDS_ROW  80
#define A_TILE   (128*LDS_ROW)         // 10240 B
#define B_TILE   (128*LDS_ROW)         // 10240 B
#define STAGE_B  (A_TILE + B_TILE)     // 20480 B
#define NSTAGE   4
#define SMEM_GEMM (NSTAGE*STAGE_B)     // 81920 B

__global__ void __launch_bounds__(256, 2)
gemm_mma() {
    extern __shared__ char smem[];
    const uint32_t sb = smem_u32(smem);
    const int tid  = threadIdx.x;
    const int lane = tid & 31;
    const int wid  = tid >> 5;
    const int mwarp = wid & 1;          // 2 warps along M (64 rows each)
    const int nwarp = wid >> 1;         // 4 warps along N (32 cols each)
    const int m0 = blockIdx.y * 128;
    const int n0 = blockIdx.x * 128;

    auto load_stage = [&](int s) {
        const int kb = s * 32;
        const int tap = (kb < 256) ? 0 : 1;
        const int xcol = kb - tap * 256;
        const int rowoff = tap ? 0 : -8;
        const uint32_t base = sb + (s & (NSTAGE - 1)) * STAGE_B;
#pragma unroll
        for (int q = 0; q < 4; q++) {
            const int idx = q * 256 + tid;
            if (q < 2) {                 // A : ids 0..511 (128 rows x 4 chunks)
                int row = idx >> 2, c = idx & 3;
                int gm = m0 + row + rowoff;
                int gmc = (gm >= 0) ? gm : 0;
                cp_async16(base + row * LDS_ROW + c * 16,
                           g_Xh + gmc * CH + xcol + c * 8, (gm >= 0) ? 16u : 0u);
            } else {                     // B : ids 0..511 (128 rows x 4 chunks)
                int i2 = idx - 512;
                int row = i2 >> 2, c = i2 & 3;
                cp_async16(base + A_TILE + row * LDS_ROW + c * 16,
                           g_Wp + (n0 + row) * KDIM + kb + c * 8, 16u);
            }
        }
    };

    float acc[4][4][4];
#pragma unroll
    for (int i = 0; i < 4; i++)
#pragma unroll
        for (int j = 0; j < 4; j++)
#pragma unroll
            for (int q = 0; q < 4; q++) acc[i][j][q] = 0.0f;

    const uint32_t a_off = (mwarp * 64 + (lane & 15)) * LDS_ROW + (lane >> 4) * 16;
    const uint32_t b_off = (nwarp * 32 + (lane & 7)) * LDS_ROW + ((lane >> 3) & 1) * 16;

    load_stage(0); CP_COMMIT();
    load_stage(1); CP_COMMIT();
    load_stage(2); CP_COMMIT();

    for (int s = 0; s < 16; s++) {
        CP_WAIT(2);                 // stage s resident (3 groups in flight)
        __syncthreads();            // all warps done reading buffer (s-1)&3
        if (s + 3 < 16) load_stage(s + 3);
        CP_COMMIT();                // empty group keeps WAIT(2) exact

        const uint32_t base = sb + (s & (NSTAGE - 1)) * STAGE_B;
#pragma unroll
        for (int kk = 0; kk < 2; kk++) {
            uint32_t aH[4][4];
#pragma unroll
            for (int mf = 0; mf < 4; mf++)
                ldsm_x4(aH[mf], base + a_off + mf * 16 * LDS_ROW + kk * 32);
#pragma unroll
            for (int nf = 0; nf < 4; nf++) {
                uint32_t b[2];
                ldsm_x2(b, base + A_TILE + b_off + nf * 8 * LDS_ROW + kk * 32);
#pragma unroll
                for (int mf = 0; mf < 4; mf++)
                    mma_f16(acc[mf][nf], aH[mf], b);
            }
        }
    }

    // ---- fused epilogue ----
    // b = lane>>2; t = by*16 + mwarp*8 + mf*2 + half.
    // h = (n0 + nwarp*32 + nf*8 + t4*2)>>1 = h0 + nwarp*16 + nf*4 + t4.
    __syncthreads();   // done with smem stage buffers; reuse for gate staging
    __half2* gtile = reinterpret_cast<__half2*>(smem);   // [16 t][8 b][68 pad]
    const int g4 = lane >> 2;             // batch b
    const int t4 = lane & 3;
    const int c_id = blockIdx.y * 2 + mwarp;   // 8-step chunk id
    const int h0 = n0 >> 1;
    const int bh_b = g4 * CH;

#pragma unroll
    for (int nf = 0; nf < 4; nf++) {
        const int n = n0 + nwarp * 32 + nf * 8 + t4 * 2;
        const int hl = nwarp * 16 + nf * 4 + t4;         // local h (0..63)
        const float bZ = g_biasf[n];
        const float bF = g_biasf[n + 1];
        float A = 1.0f, B = 0.0f;
#pragma unroll
        for (int mf = 0; mf < 4; mf++) {
#pragma unroll
            for (int half = 0; half < 2; half++) {
                float vz = acc[mf][nf][half * 2 + 0] + bZ;
                float vf = acc[mf][nf][half * 2 + 1] + bF;
                float z = vz * sigf(1.702f * vz);
                float f = sigf(vf);
                __half ah = __float2half_rn(1.0f - f);
                __half gh = __float2half_rn(f * z);
                const int tl = mwarp * 8 + mf * 2 + half;   // local t (0..15)
                gtile[tl * 544 + g4 * 68 + hl] = __halves2half2(ah, gh);
                float af = __half2float(ah);
                float gf = __half2float(gh);
                A *= af;
                B = fmaf(af, B, gf);
            }
        }
        g_cAB[c_id * BHTOT + bh_b + h0 + hl] = make_float2(A, B);
    }
    __syncthreads();

    // coalesced copy-out: 16 t x 8 b x 64 h = 8192 half2
    const int tg0 = blockIdx.y * 16;
#pragma unroll
    for (int it = 0; it < 32; it++) {
        int i = it * 256 + tid;
        int t = i >> 9, r = i & 511;
        int b = r >> 6, hh = r & 63;
        g_G[(tg0 + t) * BHTOT + b * CH + h0 + hh] = gtile[t * 544 + b * 68 + hh];
    }
}

// ---------------------------------------------------------------------------
// scan2w: one warp per (b,h) lane. Lane L composes chunks [16L, 16L+16)
// into 8 sub-affines of 2 chunks (= groups 8L..8L+7, GSTEP=16);
// warp-scan (Hillis-Steele, affine compose) produces all 256 group starting
// states; writes g_gH + h_last.
// grid = 256 blocks x 256 threads (2048 warps).
// Affine compose (x then y): (Ax*Ay, Ay*Bx + By).
// ---------------------------------------------------------------------------
__global__ void __launch_bounds__(256)
scan2w(const float* __restrict__ hidden, float* __restrict__ out) {
    const int lane = threadIdx.x & 31;
    const int bh = (blockIdx.x * 256 + threadIdx.x) >> 5;   // warp id = bh

    // load 16 chunk affines (independent 8B loads, high MLP)
    float2 v[16];
#pragma unroll
    for (int i = 0; i < 16; i++)
        v[i] = g_cAB[(lane * 16 + i) * BHTOT + bh];

    // compose 8 groups of 2 chunks each
    float gA[8], gB[8];
#pragma unroll
    for (int g = 0; g < 8; g++) {
        gB[g] = fmaf(v[g * 2 + 1].x, v[g * 2].y, v[g * 2 + 1].y);
        gA[g] = v[g * 2].x * v[g * 2 + 1].x;
    }
    // lane affine = g0 ... g7 composed
    float LA = gA[0], LB = gB[0];
#pragma unroll
    for (int g = 1; g < 8; g++) {
        LB = fmaf(gA[g], LB, gB[g]);
        LA *= gA[g];
    }

    // inclusive warp scan (non-commutative compose, lane order)
    float sA = LA, sB = LB;
#pragma unroll
    for (int off = 1; off < 32; off <<= 1) {
        float pA = __shfl_up_sync(0xFFFFFFFFu, sA, off);
        float pB = __shfl_up_sync(0xFFFFFFFFu, sB, off);
        if (lane >= off) {
            sB = fmaf(sA, pB, sB);      // (p then s): A = pA*sA, B = sA*pB + sB
            sA = pA * sA;
        }
    }
    // exclusive prefix
    float eA = __shfl_up_sync(0xFFFFFFFFu, sA, 1);
    float eB = __shfl_up_sync(0xFFFFFFFFu, sB, 1);
    if (lane == 0) { eA = 1.0f; eB = 0.0f; }

    const float h0 = hidden[bh];
    float h = fmaf(eA, h0, eB);                      // start of group 8*lane
#pragma unroll
    for (int g = 0; g < 8; g++) {
        g_gH[(8 * lane + g) * BHTOT + bh] = h;
        h = fmaf(gA[g], h, gB[g]);
    }

    if (lane == 31)
        out[SEQ * BHTOT + bh] = fmaf(sA, h0, sB);    // h_last
}

// ---------------------------------------------------------------------------
// scan3: replay 16-step groups from fp16 gates, 4 bh-lanes per thread
// (16B vector loads/stores, 4 independent h-chains).
// grid (4, 256) x 128 threads = 1024 blocks.
// ---------------------------------------------------------------------------
__global__ void __launch_bounds__(128)
scan3(float* __restrict__ out) {
    const int q  = blockIdx.x * 128 + threadIdx.x;   // 0..511
    const int bh = q * 4;
    const int g  = blockIdx.y;

    float4 h = *reinterpret_cast<const float4*>(g_gH + g * BHTOT + bh);
    const int tbase = g * GSTEP;
#pragma unroll
    for (int t = 0; t < GSTEP; t++) {
        const int idx = (tbase + t) * BHTOT + bh;
        uint4 raw = *reinterpret_cast<const uint4*>(g_G + idx);
        float2 a0 = __half22float2(*reinterpret_cast<__half2*>(&raw.x));
        float2 a1 = __half22float2(*reinterpret_cast<__half2*>(&raw.y));
        float2 a2 = __half22float2(*reinterpret_cast<__half2*>(&raw.z));
        float2 a3 = __half22float2(*reinterpret_cast<__half2*>(&raw.w));
        h.x = fmaf(a0.x, h.x, a0.y);
        h.y = fmaf(a1.x, h.y, a1.y);
        h.z = fmaf(a2.x, h.z, a2.y);
        h.w = fmaf(a3.x, h.w, a3.y);
        *reinterpret_cast<float4*>(out + idx) = h;
    }
}

// ---------------------------------------------------------------------------
extern "C" void kernel_launch(void* const* d_in, const int* in_sizes, int n_in,
                              void* d_out, int out_size) {
    const float* X      = (const float*)d_in[0];
    const float* hidden = (const float*)d_in[1];
    const float* Wz     = (const float*)d_in[2];
    const float* bz     = (const float*)d_in[3];
    const float* Wf     = (const float*)d_in[4];
    const float* bf     = (const float*)d_in[5];
    float* out = (float*)d_out;

    prep<<<M_TOT * CH / 4 / 256, 256>>>(X, Wz, bz, Wf, bf);

    cudaFuncSetAttribute(gemm_mma, cudaFuncAttributeMaxDynamicSharedMemorySize, SMEM_GEMM);
    gemm_mma<<<dim3(4, 256), 256, SMEM_GEMM>>>();

    scan2w<<<BHTOT / 8, 256>>>(hidden, out);
    scan3<<<dim3(4, NGROUP), 128>>>(out);
}

// round 13
// speedup vs baseline: 1.0405x; 1.0236x over previous
#include <cuda_runtime.h>
#include <cuda_fp16.h>
#include <cstdint>

// Problem constants
#define SEQ     4096
#define BATCH   8
#define CH      256
#define M_TOT   (SEQ*BATCH)      // 32768 rows (t-major, b inner: m = t*8 + b)
#define KDIM    512              // virtual K = 2 taps x 256 channels
#define NDIM    512              // interleaved: even n = Z col n/2, odd n = F col n/2
#define NCHUNK  512              // 8-timestep chunks
#define NGROUP  256              // groups of 2 chunks (16 timesteps)
#define GSTEP   16
#define BHTOT   2048             // BATCH*CH

// Scratch (static device globals; runtime allocation forbidden)
__device__ __half2 g_G[M_TOT*CH];           // per (t,b,h): (a=1-f, g=f*z) fp16
__device__ __half g_Xh[M_TOT*CH];
__device__ __half g_Wp[NDIM*KDIM];          // [n][k] K-major fp16, Z/F interleaved
__device__ float g_biasf[NDIM];             // interleaved bias
__device__ float2 g_cAB[NCHUNK*BHTOT];      // 8-step chunk affine (A,B), [c][bh]
__device__ float g_gH[NGROUP*BHTOT];        // group starting hidden state, [g][bh]

__device__ __forceinline__ float sigf(float x) {
    return __fdividef(1.0f, 1.0f + __expf(-x));
}

__device__ __forceinline__ uint32_t smem_u32(const void* p) {
    return (uint32_t)__cvta_generic_to_shared(p);
}

// ---------------------------------------------------------------------------
// Portable primitives: cp.async, ldmatrix, mma.sync fp16
// ---------------------------------------------------------------------------
__device__ __forceinline__ void cp_async16(uint32_t dst, const void* src, uint32_t sz) {
    asm volatile("cp.async.cg.shared.global [%0], [%1], 16, %2;"
                 :: "r"(dst), "l"(src), "r"(sz) : "memory");
}
#define CP_COMMIT() asm volatile("cp.async.commit_group;" ::: "memory")
#define CP_WAIT(n)  asm volatile("cp.async.wait_group %0;" :: "n"(n) : "memory")

__device__ __forceinline__ void ldsm_x4(uint32_t* r, uint32_t addr) {
    asm volatile("ldmatrix.sync.aligned.m8n8.x4.shared.b16 {%0,%1,%2,%3}, [%4];"
                 : "=r"(r[0]), "=r"(r[1]), "=r"(r[2]), "=r"(r[3]) : "r"(addr));
}
__device__ __forceinline__ void ldsm_x2(uint32_t* r, uint32_t addr) {
    asm volatile("ldmatrix.sync.aligned.m8n8.x2.shared.b16 {%0,%1}, [%2];"
                 : "=r"(r[0]), "=r"(r[1]) : "r"(addr));
}
__device__ __forceinline__ void mma_f16(float* d, const uint32_t* a, const uint32_t* b) {
    asm volatile(
        "mma.sync.aligned.m16n8k16.row.col.f32.f16.f16.f32 "
        "{%0,%1,%2,%3}, {%4,%5,%6,%7}, {%8,%9}, {%0,%1,%2,%3};"
        : "+f"(d[0]), "+f"(d[1]), "+f"(d[2]), "+f"(d[3])
        : "r"(a[0]), "r"(a[1]), "r"(a[2]), "r"(a[3]), "r"(b[0]), "r"(b[1]));
}

// ---------------------------------------------------------------------------
// prep: convert X -> fp16 AND pack interleaved fp16 weights + bias
// ---------------------------------------------------------------------------
__global__ void prep(const float* __restrict__ X,
                     const float* __restrict__ Wz, const float* __restrict__ bz,
                     const float* __restrict__ Wf, const float* __restrict__ bf) {
    int i = blockIdx.x * 256 + threadIdx.x;
    float4 v = reinterpret_cast<const float4*>(X)[i];
    __half2* ph = reinterpret_cast<__half2*>(g_Xh);
    ph[i * 2 + 0] = __half2(__float2half_rn(v.x), __float2half_rn(v.y));
    ph[i * 2 + 1] = __half2(__float2half_rn(v.z), __float2half_rn(v.w));
    if (i < NDIM * KDIM) {
        int n = i >> 9, k = i & 511;
        int h = n >> 1;
        int c   = (k < 256) ? k : (k - 256);
        int tap = (k < 256) ? 0 : 1;
        float w = ((n & 1) == 0) ? Wz[h * 512 + c * 2 + tap]
                                 : Wf[h * 512 + c * 2 + tap];
        g_Wp[i] = __float2half_rn(w);
    }
    if (i < NDIM) g_biasf[i] = ((i & 1) == 0) ? bz[i >> 1] : bf[i >> 1];
}

// ---------------------------------------------------------------------------
// HMMA GEMM + fused gate epilogue + 8-step chunk composition.
// CTA tile 128(M) x 128(N); grid = (4 n-tiles, 256 m-tiles); 2 CTAs/SM.
// 8 warps = 2M x 4N; warp tile 64x32.
// m = t*8 + b: lane owns batch b=lane>>2, timesteps t = by*16+mwarp*8+mf*2+half.
// Epilogue: activations -> (a,g) fp16 gates staged via smem (coalesced out)
// + per-8-step-chunk affine (A,B) as float2.
// ---------------------------------------------------------------------------
#define LDS_ROW  80
#define A_TILE   (128*LDS_ROW)         // 10240 B
#define B_TILE   (128*LDS_ROW)         // 10240 B
#define STAGE_B  (A_TILE + B_TILE)     // 20480 B
#define NSTAGE   4
#define SMEM_GEMM (NSTAGE*STAGE_B)     // 81920 B

__global__ void __launch_bounds__(256, 2)
gemm_mma() {
    extern __shared__ char smem[];
    const uint32_t sb = smem_u32(smem);
    const int tid  = threadIdx.x;
    const int lane = tid & 31;
    const int wid  = tid >> 5;
    const int mwarp = wid & 1;          // 2 warps along M (64 rows each)
    const int nwarp = wid >> 1;         // 4 warps along N (32 cols each)
    const int m0 = blockIdx.y * 128;
    const int n0 = blockIdx.x * 128;

    auto load_stage = [&](int s) {
        const int kb = s * 32;
        const int tap = (kb < 256) ? 0 : 1;
        const int xcol = kb - tap * 256;
        const int rowoff = tap ? 0 : -8;
        const uint32_t base = sb + (s & (NSTAGE - 1)) * STAGE_B;
#pragma unroll
        for (int q = 0; q < 4; q++) {
            const int idx = q * 256 + tid;
            if (q < 2) {                 // A : ids 0..511 (128 rows x 4 chunks)
                int row = idx >> 2, c = idx & 3;
                int gm = m0 + row + rowoff;
                int gmc = (gm >= 0) ? gm : 0;
                cp_async16(base + row * LDS_ROW + c * 16,
                           g_Xh + gmc * CH + xcol + c * 8, (gm >= 0) ? 16u : 0u);
            } else {                     // B : ids 0..511 (128 rows x 4 chunks)
                int i2 = idx - 512;
                int row = i2 >> 2, c = i2 & 3;
                cp_async16(base + A_TILE + row * LDS_ROW + c * 16,
                           g_Wp + (n0 + row) * KDIM + kb + c * 8, 16u);
            }
        }
    };

    float acc[4][4][4];
#pragma unroll
    for (int i = 0; i < 4; i++)
#pragma unroll
        for (int j = 0; j < 4; j++)
#pragma unroll
            for (int q = 0; q < 4; q++) acc[i][j][q] = 0.0f;

    const uint32_t a_off = (mwarp * 64 + (lane & 15)) * LDS_ROW + (lane >> 4) * 16;
    const uint32_t b_off = (nwarp * 32 + (lane & 7)) * LDS_ROW + ((lane >> 3) & 1) * 16;

    load_stage(0); CP_COMMIT();
    load_stage(1); CP_COMMIT();
    load_stage(2); CP_COMMIT();

    for (int s = 0; s < 16; s++) {
        CP_WAIT(2);                 // stage s resident (3 groups in flight)
        __syncthreads();            // all warps done reading buffer (s-1)&3
        if (s + 3 < 16) load_stage(s + 3);
        CP_COMMIT();                // empty group keeps WAIT(2) exact

        const uint32_t base = sb + (s & (NSTAGE - 1)) * STAGE_B;
#pragma unroll
        for (int kk = 0; kk < 2; kk++) {
            uint32_t aH[4][4];
#pragma unroll
            for (int mf = 0; mf < 4; mf++)
                ldsm_x4(aH[mf], base + a_off + mf * 16 * LDS_ROW + kk * 32);
#pragma unroll
            for (int nf = 0; nf < 4; nf++) {
                uint32_t b[2];
                ldsm_x2(b, base + A_TILE + b_off + nf * 8 * LDS_ROW + kk * 32);
#pragma unroll
                for (int mf = 0; mf < 4; mf++)
                    mma_f16(acc[mf][nf], aH[mf], b);
            }
        }
    }

    // ---- fused epilogue ----
    // b = lane>>2; t = by*16 + mwarp*8 + mf*2 + half.
    // h = (n0 + nwarp*32 + nf*8 + t4*2)>>1 = h0 + nwarp*16 + nf*4 + t4.
    __syncthreads();   // done with smem stage buffers; reuse for gate staging
    __half2* gtile = reinterpret_cast<__half2*>(smem);   // [16 t][8 b][68 pad]
    const int g4 = lane >> 2;             // batch b
    const int t4 = lane & 3;
    const int c_id = blockIdx.y * 2 + mwarp;   // 8-step chunk id
    const int h0 = n0 >> 1;
    const int bh_b = g4 * CH;

#pragma unroll
    for (int nf = 0; nf < 4; nf++) {
        const int n = n0 + nwarp * 32 + nf * 8 + t4 * 2;
        const int hl = nwarp * 16 + nf * 4 + t4;         // local h (0..63)
        const float bZ = g_biasf[n];
        const float bF = g_biasf[n + 1];
        float A = 1.0f, B = 0.0f;
#pragma unroll
        for (int mf = 0; mf < 4; mf++) {
#pragma unroll
            for (int half = 0; half < 2; half++) {
                float vz = acc[mf][nf][half * 2 + 0] + bZ;
                float vf = acc[mf][nf][half * 2 + 1] + bF;
                float z = vz * sigf(1.702f * vz);
                float f = sigf(vf);
                __half ah = __float2half_rn(1.0f - f);
                __half gh = __float2half_rn(f * z);
                const int tl = mwarp * 8 + mf * 2 + half;   // local t (0..15)
                gtile[tl * 544 + g4 * 68 + hl] = __halves2half2(ah, gh);
                float af = __half2float(ah);
                float gf = __half2float(gh);
                A *= af;
                B = fmaf(af, B, gf);
            }
        }
        g_cAB[c_id * BHTOT + bh_b + h0 + hl] = make_float2(A, B);
    }
    __syncthreads();

    // coalesced copy-out: 16 t x 8 b x 64 h = 8192 half2
    const int tg0 = blockIdx.y * 16;
#pragma unroll
    for (int it = 0; it < 32; it++) {
        int i = it * 256 + tid;
        int t = i >> 9, r = i & 511;
        int b = r >> 6, hh = r & 63;
        g_G[(tg0 + t) * BHTOT + b * CH + h0 + hh] = gtile[t * 544 + b * 68 + hh];
    }
}

// ---------------------------------------------------------------------------
// scan2w: one warp per (b,h) lane. Lane L composes chunks [16L, 16L+16)
// into 8 sub-affines of 2 chunks (= groups 8L..8L+7, GSTEP=16);
// warp-scan (Hillis-Steele, affine compose) produces all 256 group starting
// states; writes g_gH + h_last.
// grid = 256 blocks x 256 threads (2048 warps).
// Affine compose (x then y): (Ax*Ay, Ay*Bx + By).
// ---------------------------------------------------------------------------
__global__ void __launch_bounds__(256)
scan2w(const float* __restrict__ hidden, float* __restrict__ out) {
    const int lane = threadIdx.x & 31;
    const int bh = (blockIdx.x * 256 + threadIdx.x) >> 5;   // warp id = bh

    // load 16 chunk affines (independent 8B loads, high MLP)
    float2 v[16];
#pragma unroll
    for (int i = 0; i < 16; i++)
        v[i] = g_cAB[(lane * 16 + i) * BHTOT + bh];

    // compose 8 groups of 2 chunks each
    float gA[8], gB[8];
#pragma unroll
    for (int g = 0; g < 8; g++) {
        gB[g] = fmaf(v[g * 2 + 1].x, v[g * 2].y, v[g * 2 + 1].y);
        gA[g] = v[g * 2].x * v[g * 2 + 1].x;
    }
    // lane affine = g0 ... g7 composed
    float LA = gA[0], LB = gB[0];
#pragma unroll
    for (int g = 1; g < 8; g++) {
        LB = fmaf(gA[g], LB, gB[g]);
        LA *= gA[g];
    }

    // inclusive warp scan (non-commutative compose, lane order)
    float sA = LA, sB = LB;
#pragma unroll
    for (int off = 1; off < 32; off <<= 1) {
        float pA = __shfl_up_sync(0xFFFFFFFFu, sA, off);
        float pB = __shfl_up_sync(0xFFFFFFFFu, sB, off);
        if (lane >= off) {
            sB = fmaf(sA, pB, sB);      // (p then s): A = pA*sA, B = sA*pB + sB
            sA = pA * sA;
        }
    }
    // exclusive prefix
    float eA = __shfl_up_sync(0xFFFFFFFFu, sA, 1);
    float eB = __shfl_up_sync(0xFFFFFFFFu, sB, 1);
    if (lane == 0) { eA = 1.0f; eB = 0.0f; }

    const float h0 = hidden[bh];
    float h = fmaf(eA, h0, eB);                      // start of group 8*lane
#pragma unroll
    for (int g = 0; g < 8; g++) {
        g_gH[(8 * lane + g) * BHTOT + bh] = h;
        h = fmaf(gA[g], h, gB[g]);
    }

    if (lane == 31)
        out[SEQ * BHTOT + bh] = fmaf(sA, h0, sB);    // h_last
}

// ---------------------------------------------------------------------------
// scan3: replay 16-step groups from fp16 gates, 4 bh-lanes per thread,
// 1-deep software prefetch + streaming cache hints (single-use data).
// grid (4, 256) x 128 threads = 1024 blocks.
// ---------------------------------------------------------------------------
__global__ void __launch_bounds__(128)
scan3(float* __restrict__ out) {
    const int q  = blockIdx.x * 128 + threadIdx.x;   // 0..511
    const int bh = q * 4;
    const int g  = blockIdx.y;

    float4 h = *reinterpret_cast<const float4*>(g_gH + g * BHTOT + bh);
    const int tbase = g * GSTEP;
    const uint4* gp = reinterpret_cast<const uint4*>(g_G + tbase * BHTOT + bh);
    float4* op = reinterpret_cast<float4*>(out + tbase * BHTOT + bh);
    const int stride4 = BHTOT / 4;                   // uint4/float4 row stride

    uint4 raw = __ldcs(gp);
#pragma unroll
    for (int t = 0; t < GSTEP; t++) {
        uint4 nxt;
        if (t + 1 < GSTEP) nxt = __ldcs(gp + (t + 1) * stride4);
        float2 a0 = __half22float2(*reinterpret_cast<__half2*>(&raw.x));
        float2 a1 = __half22float2(*reinterpret_cast<__half2*>(&raw.y));
        float2 a2 = __half22float2(*reinterpret_cast<__half2*>(&raw.z));
        float2 a3 = __half22float2(*reinterpret_cast<__half2*>(&raw.w));
        h.x = fmaf(a0.x, h.x, a0.y);
        h.y = fmaf(a1.x, h.y, a1.y);
        h.z = fmaf(a2.x, h.z, a2.y);
        h.w = fmaf(a3.x, h.w, a3.y);
        __stcs(op + t * stride4, h);
        raw = nxt;
    }
}

// ---------------------------------------------------------------------------
extern "C" void kernel_launch(void* const* d_in, const int* in_sizes, int n_in,
                              void* d_out, int out_size) {
    const float* X      = (const float*)d_in[0];
    const float* hidden = (const float*)d_in[1];
    const float* Wz     = (const float*)d_in[2];
    const float* bz     = (const float*)d_in[3];
    const float* Wf     = (const float*)d_in[4];
    const float* bf     = (const float*)d_in[5];
    float* out = (float*)d_out;

    prep<<<M_TOT * CH / 4 / 256, 256>>>(X, Wz, bz, Wf, bf);

    cudaFuncSetAttribute(gemm_mma, cudaFuncAttributeMaxDynamicSharedMemorySize, SMEM_GEMM);
    gemm_mma<<<dim3(4, 256), 256, SMEM_GEMM>>>();

    scan2w<<<BHTOT / 8, 256>>>(hidden, out);
    scan3<<<dim3(4, NGROUP), 128>>>(out);
}